// round 15
// baseline (speedup 1.0000x reference)
#include <cuda_runtime.h>
#include <cuda_fp16.h>
#include <cstdint>

#define HIDDEN 1024
#define NHEADS 16
#define HDIM 64
#define BATCH 2
#define SEQ 2048
#define MTOT (BATCH*SEQ)

typedef unsigned long long ull;

// ---- fp16 scratch -----------------------------------------------------------
__device__ __half g_xh[(size_t)MTOT * HIDDEN];            // x rounded
__device__ __half g_wqkvT_h[(size_t)3 * HIDDEN * HIDDEN]; // Wqkv^T rounded
__device__ __half g_woutT_h[(size_t)HIDDEN * HIDDEN];     // Wout^T rounded
__device__ __half g_ctxh[(size_t)MTOT * HIDDEN];
__device__ __half g_ctxl[(size_t)MTOT * HIDDEN];
// attention operands, [B,h,S,d]; q pre-scaled by 0.125
__device__ __half g_qh[(size_t)MTOT * HIDDEN];   // q rounded (2-term S)
__device__ __half g_kh[(size_t)MTOT * HIDDEN];
__device__ __half g_kl[(size_t)MTOT * HIDDEN];
__device__ __half g_vh[(size_t)MTOT * HIDDEN];   // v rounded (2-term PV)

// ======================= helpers ============================================
__device__ __forceinline__ uint32_t smem_u32(const void* p) {
    uint32_t a;
    asm("{ .reg .u64 t; cvta.to.shared.u64 t, %1; cvt.u32.u64 %0, t; }"
        : "=r"(a) : "l"(p));
    return a;
}
__device__ __forceinline__ void ldm4(uint32_t& r0, uint32_t& r1,
                                     uint32_t& r2, uint32_t& r3, uint32_t a) {
    asm volatile("ldmatrix.sync.aligned.m8n8.x4.shared.b16 {%0,%1,%2,%3}, [%4];"
                 : "=r"(r0), "=r"(r1), "=r"(r2), "=r"(r3) : "r"(a));
}
__device__ __forceinline__ void ldm4t(uint32_t& r0, uint32_t& r1,
                                      uint32_t& r2, uint32_t& r3, uint32_t a) {
    asm volatile("ldmatrix.sync.aligned.m8n8.x4.trans.shared.b16 {%0,%1,%2,%3}, [%4];"
                 : "=r"(r0), "=r"(r1), "=r"(r2), "=r"(r3) : "r"(a));
}
__device__ __forceinline__ void mma_f16(float d[4], const uint32_t a[4],
                                        const uint32_t b[2]) {
    asm volatile(
        "mma.sync.aligned.m16n8k16.row.col.f32.f16.f16.f32 "
        "{%0,%1,%2,%3}, {%4,%5,%6,%7}, {%8,%9}, {%0,%1,%2,%3};"
        : "+f"(d[0]), "+f"(d[1]), "+f"(d[2]), "+f"(d[3])
        : "r"(a[0]), "r"(a[1]), "r"(a[2]), "r"(a[3]), "r"(b[0]), "r"(b[1]));
}
__device__ __forceinline__ void mma_f16a(uint32_t d[2], const uint32_t a[4],
                                         const uint32_t b[2]) {
    asm volatile(
        "mma.sync.aligned.m16n8k16.row.col.f16.f16.f16.f16 "
        "{%0,%1}, {%2,%3,%4,%5}, {%6,%7}, {%0,%1};"
        : "+r"(d[0]), "+r"(d[1])
        : "r"(a[0]), "r"(a[1]), "r"(a[2]), "r"(a[3]), "r"(b[0]), "r"(b[1]));
}
__device__ __forceinline__ void merge_res(float acc[4], const uint32_t r[2]) {
    __half2 h0 = *(const __half2*)&r[0];
    __half2 h1 = *(const __half2*)&r[1];
    float2 f0 = __half22float2(h0), f1 = __half22float2(h1);
    acc[0] += f0.x; acc[1] += f0.y;
    acc[2] += f1.x; acc[3] += f1.y;
}
__device__ __forceinline__ void cpa16(uint32_t dst, const void* src) {
    asm volatile("cp.async.cg.shared.global [%0], [%1], 16;"
                 :: "r"(dst), "l"(src) : "memory");
}
#define CP_COMMIT() asm volatile("cp.async.commit_group;" ::: "memory")
#define CP_WAIT2()  asm volatile("cp.async.wait_group 2;" ::: "memory")
#define CP_WAIT1()  asm volatile("cp.async.wait_group 1;" ::: "memory")
#define CP_WAIT0()  asm volatile("cp.async.wait_group 0;" ::: "memory")

__device__ __forceinline__ void split22(float a, float b, uint32_t& h, uint32_t& l) {
    __half2 hh = __floats2half2_rn(a, b);
    float2 f = __half22float2(hh);
    __half2 ll = __floats2half2_rn(a - f.x, b - f.y);
    h = *(uint32_t*)&hh;
    l = *(uint32_t*)&ll;
}
__device__ __forceinline__ uint32_t round22(float a, float b) {
    __half2 hh = __floats2half2_rn(a, b);
    return *(uint32_t*)&hh;
}

#define ASTR 40
#define BUFH (128 * ASTR)
#define NSTAGE 3
#define GEMM1_SMEM_BYTES (NSTAGE * 2 * BUFH * 2)
#define GEMM2_SMEM_BYTES (NSTAGE * 3 * BUFH * 2)

// ---------------------------------------------------------------------------
// Conversion kernels
// ---------------------------------------------------------------------------
__global__ __launch_bounds__(256) void conv_x_round(
    const float* __restrict__ src, __half* __restrict__ dh, int n4)
{
    int i = blockIdx.x * 256 + threadIdx.x;
    if (i >= n4) return;
    float4 v = ((const float4*)src)[i];
    ((uint2*)dh)[i] = make_uint2(round22(v.x, v.y), round22(v.z, v.w));
}

__global__ __launch_bounds__(256) void conv_wT_kernel(
    const float* __restrict__ W, __half* __restrict__ WhT, int N)
{
    __shared__ float ts[32][33];
    int n0 = blockIdx.x * 32, k0 = blockIdx.y * 32;
    int tx = threadIdx.x & 31, ty = threadIdx.x >> 5;
#pragma unroll
    for (int r = 0; r < 32; r += 8)
        ts[ty + r][tx] = W[(size_t)(k0 + ty + r) * N + n0 + tx];
    __syncthreads();
#pragma unroll
    for (int r = 0; r < 32; r += 8) {
        float v = ts[tx][ty + r];
        size_t o = (size_t)(n0 + ty + r) * HIDDEN + k0 + tx;
        WhT[o] = __float2half_rn(v);
    }
}

// ---------------------------------------------------------------------------
// 1-term HMMA GEMM mainloop (qkv): D = xh @ Wh. 256 thr, 8 warps 32x64.
// ---------------------------------------------------------------------------
__device__ __forceinline__ void stage_chunk2(
    const __half* __restrict__ Ah, const __half* __restrict__ BhT,
    int bm, int bn, int k0, int tid, uint32_t sbuf)
{
    for (int i = tid; i < 512; i += 256) {
        int row = i >> 2, q = i & 3;
        uint32_t doff = (uint32_t)((row * ASTR + q * 8) * 2);
        cpa16(sbuf + doff,            Ah + (size_t)(bm + row) * HIDDEN + k0 + q * 8);
        cpa16(sbuf + BUFH * 2 + doff, BhT + (size_t)(bn + row) * HIDDEN + k0 + q * 8);
    }
}

__device__ __forceinline__ void hmma_gemm_main1(
    const __half* __restrict__ Ah, const __half* __restrict__ BhT,
    int bm, int bn, int tid, uint32_t sbase, float acc[2][8][4])
{
    const int lane = tid & 31, wid = tid >> 5;
    const int m_off = (wid & 3) * 32, n_off = (wid >> 2) * 64;
    const int arow = lane & 15;
    const int acolb = (lane >> 4) << 3;
    const int brow = (lane & 7) + ((lane >> 4) << 3);
    const int bcolb = ((lane >> 3) & 1) << 3;
    const uint32_t bufbytes = 2 * BUFH * 2;

    stage_chunk2(Ah, BhT, bm, bn, 0, tid, sbase);
    CP_COMMIT();
    stage_chunk2(Ah, BhT, bm, bn, 32, tid, sbase + bufbytes);
    CP_COMMIT();

    for (int c = 0; c < 32; c++) {
        uint32_t cur = sbase + (uint32_t)(c % 3) * bufbytes;
        if (c + 1 < 32) { CP_WAIT1(); } else { CP_WAIT0(); }
        __syncthreads();
        if (c + 2 < 32) {
            stage_chunk2(Ah, BhT, bm, bn, (c + 2) * 32, tid,
                         sbase + (uint32_t)((c + 2) % 3) * bufbytes);
            CP_COMMIT();
        }

        uint32_t uAh = cur, uBh = cur + BUFH * 2;
#pragma unroll
        for (int kk = 0; kk < 32; kk += 16) {
            uint32_t aH[2][4], bH[8][2];
#pragma unroll
            for (int t = 0; t < 2; t++) {
                uint32_t off = (uint32_t)(((m_off + t * 16 + arow) * ASTR
                                           + kk + acolb) * 2);
                ldm4(aH[t][0], aH[t][1], aH[t][2], aH[t][3], uAh + off);
            }
#pragma unroll
            for (int p = 0; p < 4; p++) {
                uint32_t off = (uint32_t)(((n_off + p * 16 + brow) * ASTR
                                           + kk + bcolb) * 2);
                ldm4(bH[2 * p][0], bH[2 * p][1], bH[2 * p + 1][0], bH[2 * p + 1][1],
                     uBh + off);
            }
#pragma unroll
            for (int mt = 0; mt < 2; mt++)
#pragma unroll
                for (int nt = 0; nt < 8; nt++)
                    mma_f16(acc[mt][nt], aH[mt], bH[nt]);
        }
    }
}

// ---------------------------------------------------------------------------
// 2-term HMMA GEMM mainloop (out-proj): D = (Ah+Al) @ Bh
// ---------------------------------------------------------------------------
__device__ __forceinline__ void stage_chunk3(
    const __half* __restrict__ Ah, const __half* __restrict__ Al,
    const __half* __restrict__ BhT,
    int bm, int bn, int k0, int tid, uint32_t sbuf)
{
    for (int i = tid; i < 512; i += 256) {
        int row = i >> 2, q = i & 3;
        uint32_t doff = (uint32_t)((row * ASTR + q * 8) * 2);
        size_t soA = (size_t)(bm + row) * HIDDEN + k0 + q * 8;
        size_t soB = (size_t)(bn + row) * HIDDEN + k0 + q * 8;
        cpa16(sbuf + doff,                Ah + soA);
        cpa16(sbuf + BUFH * 2 + doff,     Al + soA);
        cpa16(sbuf + 2 * BUFH * 2 + doff, BhT + soB);
    }
}

__device__ __forceinline__ void hmma_gemm_main2(
    const __half* __restrict__ Ah, const __half* __restrict__ Al,
    const __half* __restrict__ BhT,
    int bm, int bn, int tid, uint32_t sbase,
    float acc[2][8][4], uint32_t accH[2][8][2])
{
    const int lane = tid & 31, wid = tid >> 5;
    const int m_off = (wid & 3) * 32, n_off = (wid >> 2) * 64;
    const int arow = lane & 15;
    const int acolb = (lane >> 4) << 3;
    const int brow = (lane & 7) + ((lane >> 4) << 3);
    const int bcolb = ((lane >> 3) & 1) << 3;
    const uint32_t bufbytes = 3 * BUFH * 2;

    stage_chunk3(Ah, Al, BhT, bm, bn, 0, tid, sbase);
    CP_COMMIT();
    stage_chunk3(Ah, Al, BhT, bm, bn, 32, tid, sbase + bufbytes);
    CP_COMMIT();

    for (int c = 0; c < 32; c++) {
        uint32_t cur = sbase + (uint32_t)(c % 3) * bufbytes;
        if (c + 1 < 32) { CP_WAIT1(); } else { CP_WAIT0(); }
        __syncthreads();
        if (c + 2 < 32) {
            stage_chunk3(Ah, Al, BhT, bm, bn, (c + 2) * 32, tid,
                         sbase + (uint32_t)((c + 2) % 3) * bufbytes);
            CP_COMMIT();
        }

        uint32_t uAh = cur, uAl = cur + BUFH * 2;
        uint32_t uBh = cur + 2 * BUFH * 2;
#pragma unroll
        for (int kk = 0; kk < 32; kk += 16) {
            uint32_t aH[2][4], aL[2][4], bH[8][2];
#pragma unroll
            for (int t = 0; t < 2; t++) {
                uint32_t off = (uint32_t)(((m_off + t * 16 + arow) * ASTR
                                           + kk + acolb) * 2);
                ldm4(aH[t][0], aH[t][1], aH[t][2], aH[t][3], uAh + off);
                ldm4(aL[t][0], aL[t][1], aL[t][2], aL[t][3], uAl + off);
            }
#pragma unroll
            for (int p = 0; p < 4; p++) {
                uint32_t off = (uint32_t)(((n_off + p * 16 + brow) * ASTR
                                           + kk + bcolb) * 2);
                ldm4(bH[2 * p][0], bH[2 * p][1], bH[2 * p + 1][0], bH[2 * p + 1][1],
                     uBh + off);
            }
#pragma unroll
            for (int mt = 0; mt < 2; mt++)
#pragma unroll
                for (int nt = 0; nt < 8; nt++) {
                    mma_f16(acc[mt][nt], aH[mt], bH[nt]);
                    mma_f16a(accH[mt][nt], aL[mt], bH[nt]);
                }
        }
    }
}

// ---------------------------------------------------------------------------
// GEMM 1 (1-term): qkv = xh @ Wh + b -> fp32 q/k/v + fused fp16 attn copies
// ---------------------------------------------------------------------------
__global__ __launch_bounds__(256, 1) void gemm_qkv_mma(
    const float* __restrict__ bias,
    float* __restrict__ qo, float* __restrict__ ko, float* __restrict__ vo)
{
    extern __shared__ __half dynsm[];
    int tid = threadIdx.x, lane = tid & 31, wid = tid >> 5;
    int bm = blockIdx.y * 128, bn = blockIdx.x * 128;
    float acc[2][8][4] = {};

    hmma_gemm_main1(g_xh, g_wqkvT_h, bm, bn, tid, smem_u32(dynsm), acc);

    const int m_off = (wid & 3) * 32, n_off = (wid >> 2) * 64;
    int r = lane >> 2, c2 = (lane & 3) << 1;
#pragma unroll
    for (int mt = 0; mt < 2; mt++) {
        int m0 = bm + m_off + mt * 16 + r;
        int m1 = m0 + 8;
        int bb0 = m0 >> 11, s0 = m0 & (SEQ - 1);
        int bb1 = m1 >> 11, s1 = m1 & (SEQ - 1);
#pragma unroll
        for (int nt = 0; nt < 8; nt++) {
            int n = bn + n_off + nt * 8 + c2;
            float2 bv = *(const float2*)&bias[n];
            int t = n >> 10, hh = (n >> 6) & 15, dc = n & 63;
            float* base = (t == 0) ? qo : ((t == 1) ? ko : vo);
            float v00 = acc[mt][nt][0] + bv.x, v01 = acc[mt][nt][1] + bv.y;
            float v10 = acc[mt][nt][2] + bv.x, v11 = acc[mt][nt][3] + bv.y;
            size_t off0 = ((size_t)(bb0 * NHEADS + hh) * SEQ + s0) * HDIM + dc;
            size_t off1 = ((size_t)(bb1 * NHEADS + hh) * SEQ + s1) * HDIM + dc;
            *(float2*)&base[off0] = make_float2(v00, v01);
            *(float2*)&base[off1] = make_float2(v10, v11);
            if (t == 0) {
                *(uint32_t*)&g_qh[off0] = round22(v00 * 0.125f, v01 * 0.125f);
                *(uint32_t*)&g_qh[off1] = round22(v10 * 0.125f, v11 * 0.125f);
            } else if (t == 1) {
                uint32_t h2, l2;
                split22(v00, v01, h2, l2);
                *(uint32_t*)&g_kh[off0] = h2; *(uint32_t*)&g_kl[off0] = l2;
                split22(v10, v11, h2, l2);
                *(uint32_t*)&g_kh[off1] = h2; *(uint32_t*)&g_kl[off1] = l2;
            } else {
                *(uint32_t*)&g_vh[off0] = round22(v00, v01);
                *(uint32_t*)&g_vh[off1] = round22(v10, v11);
            }
        }
    }
}

// ---------------------------------------------------------------------------
// GEMM 2: output = (ctxh+ctxl) @ Wouth + b_out (2-term)
// ---------------------------------------------------------------------------
__global__ __launch_bounds__(256, 1) void gemm_out_mma(
    const float* __restrict__ bias, float* __restrict__ C)
{
    extern __shared__ __half dynsm[];
    int tid = threadIdx.x, lane = tid & 31, wid = tid >> 5;
    int bm = blockIdx.y * 128, bn = blockIdx.x * 128;
    float acc[2][8][4] = {};
    uint32_t accH[2][8][2] = {};

    hmma_gemm_main2(g_ctxh, g_ctxl, g_woutT_h, bm, bn, tid,
                    smem_u32(dynsm), acc, accH);

    const int m_off = (wid & 3) * 32, n_off = (wid >> 2) * 64;
    int r = lane >> 2, c2 = (lane & 3) << 1;
#pragma unroll
    for (int mt = 0; mt < 2; mt++) {
        int m0 = bm + m_off + mt * 16 + r;
        int m1 = m0 + 8;
#pragma unroll
        for (int nt = 0; nt < 8; nt++) {
            merge_res(acc[mt][nt], accH[mt][nt]);
            int n = bn + n_off + nt * 8 + c2;
            float2 bv = *(const float2*)&bias[n];
            *(float2*)&C[(size_t)m0 * HIDDEN + n] =
                make_float2(acc[mt][nt][0] + bv.x, acc[mt][nt][1] + bv.y);
            *(float2*)&C[(size_t)m1 * HIDDEN + n] =
                make_float2(acc[mt][nt][2] + bv.x, acc[mt][nt][3] + bv.y);
        }
    }
}

// ---------------------------------------------------------------------------
// Flash attention on HMMA (unchanged from round 14): 2-term S, 2-term PV.
// ---------------------------------------------------------------------------
#define KT 64
#define QT 128
#define AST2 72
#define QARR (128 * AST2)
#define KV_OFF QARR
#define ARR2 (64 * AST2)
#define KVBUF (3 * ARR2)
#define NKV 3
#define ATTN_SMEM_BYTES ((KV_OFF + NKV * KVBUF) * 2 + 2 * 64 * 4)

__device__ __forceinline__ void stage_kv(
    const __half* Kh, const __half* Kl, const __half* Vh,
    int k0, int tid, uint32_t sbuf)
{
    for (int i = tid; i < 512; i += 256) {
        int row = i >> 3, q = i & 7;
        uint32_t doff = (uint32_t)((row * AST2 + q * 8) * 2);
        size_t src = (size_t)(k0 + row) * HDIM + q * 8;
        cpa16(sbuf + doff,                Kh + src);
        cpa16(sbuf + ARR2 * 2 + doff,     Kl + src);
        cpa16(sbuf + 2 * ARR2 * 2 + doff, Vh + src);
    }
}

__global__ __launch_bounds__(256, 1) void attn_mma(const int* __restrict__ mask)
{
    extern __shared__ __half asm_[];
    uint32_t sb = smem_u32(asm_);
    float* mbias = (float*)(asm_ + KV_OFF + NKV * KVBUF);
    int tid = threadIdx.x, lane = tid & 31, wid = tid >> 5;
    int qt = gridDim.x - 1 - blockIdx.x;      // long tiles first
    int h = blockIdx.y, b = blockIdx.z;
    int bh = b * NHEADS + h;
    int qbase = qt * QT;
    size_t qoff = ((size_t)bh * SEQ + qbase) * HDIM;
    const __half* Qh = g_qh + qoff;
    size_t kvoff = (size_t)bh * SEQ * HDIM;
    const __half *Kh = g_kh + kvoff, *Kl = g_kl + kvoff;
    const __half *Vh = g_vh + kvoff;

    for (int i = tid; i < 1024; i += 256) {
        int row = i >> 3, q = i & 7;
        uint32_t doff = (uint32_t)((row * AST2 + q * 8) * 2);
        cpa16(sb + doff, Qh + (size_t)row * HDIM + q * 8);
    }
    CP_COMMIT();

    const int nkt = 2 * qt + 2;
    stage_kv(Kh, Kl, Vh, 0, tid, sb + KV_OFF * 2);
    CP_COMMIT();
    stage_kv(Kh, Kl, Vh, KT, tid, sb + (KV_OFF + KVBUF) * 2);
    CP_COMMIT();
    CP_WAIT2();          // Q ready
    __syncthreads();

    const int m_off = wid * 16;
    uint32_t qah[4][4];
    {
        int row = m_off + (lane & 15);
        int colb = 8 * (lane >> 4);
#pragma unroll
        for (int kt2 = 0; kt2 < 4; kt2++) {
            uint32_t a = sb + (uint32_t)((row * AST2 + kt2 * 16 + colb) * 2);
            ldm4(qah[kt2][0], qah[kt2][1], qah[kt2][2], qah[kt2][3], a);
        }
    }

    float o[8][4] = {};
    float m0 = -1e30f, m1 = -1e30f, l0 = 0.f, l1 = 0.f;
    const int g = lane >> 2, c2 = (lane & 3) << 1;
    const int brow = (lane & 7) + ((lane >> 4) << 3);
    const int bcolb = ((lane >> 3) & 1) << 3;
    const int vrow = lane & 15, vcolb = 8 * (lane >> 4);
    const int row0 = qbase + m_off + g, row1 = row0 + 8;

    for (int c = 0; c < nkt; c++) {
        uint32_t cur = sb + (uint32_t)((KV_OFF + (c % 3) * KVBUF) * 2);
        if (c + 1 < nkt) { CP_WAIT1(); } else { CP_WAIT0(); }
        if (tid < 64)
            mbias[(c & 1) * 64 + tid] =
                (mask[b * SEQ + c * KT + tid] == 0) ? -1e30f : 0.0f;
        __syncthreads();
        if (c + 2 < nkt) {
            stage_kv(Kh, Kl, Vh, (c + 2) * KT, tid,
                     sb + (uint32_t)((KV_OFF + ((c + 2) % 3) * KVBUF) * 2));
            CP_COMMIT();
        }

        uint32_t uKh = cur, uKl = cur + ARR2 * 2;
        uint32_t uVh = cur + 2 * ARR2 * 2;

        // ---- S = qh (kh + kl)^T : 2-term ----
        float s[8][4] = {};
        uint32_t sres[8][2] = {};
#pragma unroll
        for (int kk2 = 0; kk2 < 4; kk2++) {
            uint32_t kbh[4][4], kbl[4][4];
#pragma unroll
            for (int p = 0; p < 4; p++) {
                uint32_t a = (uint32_t)(((p * 16 + brow) * AST2
                                         + kk2 * 16 + bcolb) * 2);
                ldm4(kbh[p][0], kbh[p][1], kbh[p][2], kbh[p][3], uKh + a);
                ldm4(kbl[p][0], kbl[p][1], kbl[p][2], kbl[p][3], uKl + a);
            }
#pragma unroll
            for (int nt = 0; nt < 8; nt++) {
                int p = nt >> 1, ix = (nt & 1) * 2;
                mma_f16(s[nt], qah[kk2], &kbh[p][ix]);
                mma_f16a(sres[nt], qah[kk2], &kbl[p][ix]);
            }
        }
#pragma unroll
        for (int nt = 0; nt < 8; nt++) merge_res(s[nt], sres[nt]);

        // ---- mask + causal ----
        int k0 = c * KT;
        bool diag = (k0 + KT - 1 > row0) || (k0 + KT - 1 > row1);
#pragma unroll
        for (int nt = 0; nt < 8; nt++) {
            int colb = k0 + nt * 8 + c2;
            float mb0 = mbias[(c & 1) * 64 + nt * 8 + c2];
            float mb1 = mbias[(c & 1) * 64 + nt * 8 + c2 + 1];
            s[nt][0] += mb0; s[nt][1] += mb1;
            s[nt][2] += mb0; s[nt][3] += mb1;
            if (diag) {
                if (colb     > row0) s[nt][0] = -1e30f;
                if (colb + 1 > row0) s[nt][1] = -1e30f;
                if (colb     > row1) s[nt][2] = -1e30f;
                if (colb + 1 > row1) s[nt][3] = -1e30f;
            }
        }

        // ---- online softmax ----
        float mx0 = -1e30f, mx1 = -1e30f;
#pragma unroll
        for (int nt = 0; nt < 8; nt++) {
            mx0 = fmaxf(mx0, fmaxf(s[nt][0], s[nt][1]));
            mx1 = fmaxf(mx1, fmaxf(s[nt][2], s[nt][3]));
        }
        mx0 = fmaxf(mx0, __shfl_xor_sync(0xffffffffu, mx0, 1));
        mx0 = fmaxf(mx0, __shfl_xor_sync(0xffffffffu, mx0, 2));
        mx1 = fmaxf(mx1, __shfl_xor_sync(0xffffffffu, mx1, 1));
        mx1 = fmaxf(mx1, __shfl_xor_sync(0xffffffffu, mx1, 2));
        float mn0 = fmaxf(m0, mx0), mn1 = fmaxf(m1, mx1);
        float fac0 = __expf(m0 - mn0), fac1 = __expf(m1 - mn1);
        m0 = mn0; m1 = mn1;
        float rs0 = 0.f, rs1 = 0.f;
#pragma unroll
        for (int nt = 0; nt < 8; nt++) {
            s[nt][0] = __expf(s[nt][0] - mn0); rs0 += s[nt][0];
            s[nt][1] = __expf(s[nt][1] - mn0); rs0 += s[nt][1];
            s[nt][2] = __expf(s[nt][2] - mn1); rs1 += s[nt][2];
            s[nt][3] = __expf(s[nt][3] - mn1); rs1 += s[nt][3];
        }
        rs0 += __shfl_xor_sync(0xffffffffu, rs0, 1);
        rs0 += __shfl_xor_sync(0xffffffffu, rs0, 2);
        rs1 += __shfl_xor_sync(0xffffffffu, rs1, 1);
        rs1 += __shfl_xor_sync(0xffffffffu, rs1, 2);
        l0 = l0 * fac0 + rs0;
        l1 = l1 * fac1 + rs1;
#pragma unroll
        for (int nt = 0; nt < 8; nt++) {
            o[nt][0] *= fac0; o[nt][1] *= fac0;
            o[nt][2] *= fac1; o[nt][3] *= fac1;
        }

        // ---- P fragments (split P: h + l) ----
        uint32_t pah[4][4], pal[4][4];
#pragma unroll
        for (int kt2 = 0; kt2 < 4; kt2++) {
            split22(s[2 * kt2][0],     s[2 * kt2][1],     pah[kt2][0], pal[kt2][0]);
            split22(s[2 * kt2][2],     s[2 * kt2][3],     pah[kt2][1], pal[kt2][1]);
            split22(s[2 * kt2 + 1][0], s[2 * kt2 + 1][1], pah[kt2][2], pal[kt2][2]);
            split22(s[2 * kt2 + 1][2], s[2 * kt2 + 1][3], pah[kt2][3], pal[kt2][3]);
        }

        // ---- O += (Ph + Pl) Vh : 2-term ----
        uint32_t ores[8][2] = {};
#pragma unroll
        for (int kk2 = 0; kk2 < 4; kk2++) {
            uint32_t vbh[4][4];
#pragma unroll
            for (int n0i = 0; n0i < 4; n0i++) {
                uint32_t a = (uint32_t)(((kk2 * 16 + vrow) * AST2
                                         + n0i * 16 + vcolb) * 2);
                ldm4t(vbh[n0i][0], vbh[n0i][1], vbh[n0i][2], vbh[n0i][3], uVh + a);
            }
#pragma unroll
            for (int nt = 0; nt < 8; nt++) {
                int n0i = nt >> 1, ix = (nt & 1) * 2;
                mma_f16(o[nt], pah[kk2], &vbh[n0i][ix]);
                mma_f16a(ores[nt], pal[kk2], &vbh[n0i][ix]);
            }
        }
#pragma unroll
        for (int nt = 0; nt < 8; nt++) merge_res(o[nt], ores[nt]);
    }

    // ---- epilogue: normalize, write ctx h/l ----
    float inv0 = 1.0f / l0, inv1 = 1.0f / l1;
    size_t base0 = ((size_t)(b * SEQ) + row0) * HIDDEN + h * HDIM + c2;
    size_t base1 = base0 + (size_t)8 * HIDDEN;
#pragma unroll
    for (int nt = 0; nt < 8; nt++) {
        uint32_t h2, l2;
        split22(o[nt][0] * inv0, o[nt][1] * inv0, h2, l2);
        *(uint32_t*)&g_ctxh[base0 + nt * 8] = h2;
        *(uint32_t*)&g_ctxl[base0 + nt * 8] = l2;
        split22(o[nt][2] * inv1, o[nt][3] * inv1, h2, l2);
        *(uint32_t*)&g_ctxh[base1 + nt * 8] = h2;
        *(uint32_t*)&g_ctxl[base1 + nt * 8] = l2;
    }
}

// ---------------------------------------------------------------------------
extern "C" void kernel_launch(void* const* d_in, const int* in_sizes, int n_in,
                              void* d_out, int out_size) {
    const float* x    = (const float*)d_in[0];
    const int*   mask = (const int*)d_in[1];
    const float* Wqkv = (const float*)d_in[2];
    const float* bqkv = (const float*)d_in[3];
    const float* Wout = (const float*)d_in[4];
    const float* bout = (const float*)d_in[5];

    float* out = (float*)d_out;                     // [B,S,H]
    float* qo = out + (size_t)MTOT * HIDDEN;        // [B,h,S,d]
    float* ko = qo + (size_t)MTOT * HIDDEN;
    float* vo = ko + (size_t)MTOT * HIDDEN;

    cudaFuncSetAttribute(gemm_qkv_mma,
                         cudaFuncAttributeMaxDynamicSharedMemorySize, GEMM1_SMEM_BYTES);
    cudaFuncSetAttribute(gemm_out_mma,
                         cudaFuncAttributeMaxDynamicSharedMemorySize, GEMM2_SMEM_BYTES);
    cudaFuncSetAttribute(attn_mma,
                         cudaFuncAttributeMaxDynamicSharedMemorySize, ATTN_SMEM_BYTES);

    __half *xh, *wqh, *woh;
    cudaGetSymbolAddress((void**)&xh, g_xh);
    cudaGetSymbolAddress((void**)&wqh, g_wqkvT_h);
    cudaGetSymbolAddress((void**)&woh, g_woutT_h);

    conv_x_round<<<(MTOT * HIDDEN / 4 + 255) / 256, 256>>>(
        x, xh, MTOT * HIDDEN / 4);
    conv_wT_kernel<<<dim3(3 * HIDDEN / 32, HIDDEN / 32), 256>>>(
        Wqkv, wqh, 3 * HIDDEN);
    conv_wT_kernel<<<dim3(HIDDEN / 32, HIDDEN / 32), 256>>>(
        Wout, woh, HIDDEN);

    gemm_qkv_mma<<<dim3(24, 32), 256, GEMM1_SMEM_BYTES>>>(bqkv, qo, ko, vo);
    attn_mma<<<dim3(SEQ / QT, NHEADS, BATCH), 256, ATTN_SMEM_BYTES>>>(mask);
    gemm_out_mma<<<dim3(8, 32), 256, GEMM2_SMEM_BYTES>>>(bout, out);
}

// round 16
// speedup vs baseline: 1.6242x; 1.6242x over previous
#include <cuda_runtime.h>
#include <cuda_fp16.h>
#include <cstdint>

#define HIDDEN 1024
#define NHEADS 16
#define HDIM 64
#define BATCH 2
#define SEQ 2048
#define MTOT (BATCH*SEQ)

typedef unsigned long long ull;

// ---- fp16 scratch -----------------------------------------------------------
__device__ __half g_xh[(size_t)MTOT * HIDDEN];            // x rounded
__device__ __half g_wqkvT_h[(size_t)3 * HIDDEN * HIDDEN]; // Wqkv^T rounded
__device__ __half g_woutT_h[(size_t)HIDDEN * HIDDEN];     // Wout^T rounded
__device__ __half g_ctxh[(size_t)MTOT * HIDDEN];
__device__ __half g_ctxl[(size_t)MTOT * HIDDEN];
// attention operands, [B,h,S,d]; q pre-scaled by 0.125
__device__ __half g_qh[(size_t)MTOT * HIDDEN];   // q rounded (2-term S)
__device__ __half g_kh[(size_t)MTOT * HIDDEN];
__device__ __half g_kl[(size_t)MTOT * HIDDEN];
__device__ __half g_vh[(size_t)MTOT * HIDDEN];   // v rounded (2-term PV)

// ======================= helpers ============================================
__device__ __forceinline__ uint32_t smem_u32(const void* p) {
    uint32_t a;
    asm("{ .reg .u64 t; cvta.to.shared.u64 t, %1; cvt.u32.u64 %0, t; }"
        : "=r"(a) : "l"(p));
    return a;
}
__device__ __forceinline__ void ldm4(uint32_t& r0, uint32_t& r1,
                                     uint32_t& r2, uint32_t& r3, uint32_t a) {
    asm volatile("ldmatrix.sync.aligned.m8n8.x4.shared.b16 {%0,%1,%2,%3}, [%4];"
                 : "=r"(r0), "=r"(r1), "=r"(r2), "=r"(r3) : "r"(a));
}
__device__ __forceinline__ void ldm4t(uint32_t& r0, uint32_t& r1,
                                      uint32_t& r2, uint32_t& r3, uint32_t a) {
    asm volatile("ldmatrix.sync.aligned.m8n8.x4.trans.shared.b16 {%0,%1,%2,%3}, [%4];"
                 : "=r"(r0), "=r"(r1), "=r"(r2), "=r"(r3) : "r"(a));
}
__device__ __forceinline__ void mma_f16(float d[4], const uint32_t a[4],
                                        const uint32_t b[2]) {
    asm volatile(
        "mma.sync.aligned.m16n8k16.row.col.f32.f16.f16.f32 "
        "{%0,%1,%2,%3}, {%4,%5,%6,%7}, {%8,%9}, {%0,%1,%2,%3};"
        : "+f"(d[0]), "+f"(d[1]), "+f"(d[2]), "+f"(d[3])
        : "r"(a[0]), "r"(a[1]), "r"(a[2]), "r"(a[3]), "r"(b[0]), "r"(b[1]));
}
__device__ __forceinline__ void mma_f16a(uint32_t d[2], const uint32_t a[4],
                                         const uint32_t b[2]) {
    asm volatile(
        "mma.sync.aligned.m16n8k16.row.col.f16.f16.f16.f16 "
        "{%0,%1}, {%2,%3,%4,%5}, {%6,%7}, {%0,%1};"
        : "+r"(d[0]), "+r"(d[1])
        : "r"(a[0]), "r"(a[1]), "r"(a[2]), "r"(a[3]), "r"(b[0]), "r"(b[1]));
}
__device__ __forceinline__ void merge_res(float acc[4], const uint32_t r[2]) {
    __half2 h0 = *(const __half2*)&r[0];
    __half2 h1 = *(const __half2*)&r[1];
    float2 f0 = __half22float2(h0), f1 = __half22float2(h1);
    acc[0] += f0.x; acc[1] += f0.y;
    acc[2] += f1.x; acc[3] += f1.y;
}
__device__ __forceinline__ void cpa16(uint32_t dst, const void* src) {
    asm volatile("cp.async.cg.shared.global [%0], [%1], 16;"
                 :: "r"(dst), "l"(src) : "memory");
}
#define CP_COMMIT() asm volatile("cp.async.commit_group;" ::: "memory")
#define CP_WAIT2()  asm volatile("cp.async.wait_group 2;" ::: "memory")
#define CP_WAIT1()  asm volatile("cp.async.wait_group 1;" ::: "memory")
#define CP_WAIT0()  asm volatile("cp.async.wait_group 0;" ::: "memory")

__device__ __forceinline__ void split22(float a, float b, uint32_t& h, uint32_t& l) {
    __half2 hh = __floats2half2_rn(a, b);
    float2 f = __half22float2(hh);
    __half2 ll = __floats2half2_rn(a - f.x, b - f.y);
    h = *(uint32_t*)&hh;
    l = *(uint32_t*)&ll;
}
__device__ __forceinline__ uint32_t round22(float a, float b) {
    __half2 hh = __floats2half2_rn(a, b);
    return *(uint32_t*)&hh;
}

#define ASTR 40
#define BUFH (128 * ASTR)
#define NSTAGE 3
#define GEMM2_SMEM_BYTES (NSTAGE * 3 * BUFH * 2)
// 1-term qkv gemm: K-chunk 64, row stride 72 halves
#define G1STR 72
#define G1BUF (128 * G1STR)
#define GEMM1_SMEM_BYTES (NSTAGE * 2 * G1BUF * 2)

// ---------------------------------------------------------------------------
// Conversion kernels
// ---------------------------------------------------------------------------
__global__ __launch_bounds__(256) void conv_x_round(
    const float* __restrict__ src, __half* __restrict__ dh, int n4)
{
    int i = blockIdx.x * 256 + threadIdx.x;
    if (i >= n4) return;
    float4 v = ((const float4*)src)[i];
    ((uint2*)dh)[i] = make_uint2(round22(v.x, v.y), round22(v.z, v.w));
}

__global__ __launch_bounds__(256) void conv_wT_kernel(
    const float* __restrict__ W, __half* __restrict__ WhT, int N)
{
    __shared__ float ts[32][33];
    int n0 = blockIdx.x * 32, k0 = blockIdx.y * 32;
    int tx = threadIdx.x & 31, ty = threadIdx.x >> 5;
#pragma unroll
    for (int r = 0; r < 32; r += 8)
        ts[ty + r][tx] = W[(size_t)(k0 + ty + r) * N + n0 + tx];
    __syncthreads();
#pragma unroll
    for (int r = 0; r < 32; r += 8) {
        float v = ts[tx][ty + r];
        size_t o = (size_t)(n0 + ty + r) * HIDDEN + k0 + tx;
        WhT[o] = __float2half_rn(v);
    }
}

// q/k/v fp32 [B,h,S,d] -> fp16 (q: h only, scaled 1/8; k: h+l; v: h only)
__global__ __launch_bounds__(256) void conv_attn_split(
    const float* __restrict__ q, const float* __restrict__ k,
    const float* __restrict__ v)
{
    const int n4 = MTOT * HIDDEN / 4;
    int i = blockIdx.x * 256 + threadIdx.x;
    int region = i / n4;
    int j = i - region * n4;
    if (region == 0) {
        float4 val = ((const float4*)q)[j];
        ((uint2*)g_qh)[j] = make_uint2(round22(val.x * 0.125f, val.y * 0.125f),
                                       round22(val.z * 0.125f, val.w * 0.125f));
    } else if (region == 1) {
        float4 val = ((const float4*)k)[j];
        uint32_t h0, l0, h1, l1;
        split22(val.x, val.y, h0, l0);
        split22(val.z, val.w, h1, l1);
        ((uint2*)g_kh)[j] = make_uint2(h0, h1);
        ((uint2*)g_kl)[j] = make_uint2(l0, l1);
    } else {
        float4 val = ((const float4*)v)[j];
        ((uint2*)g_vh)[j] = make_uint2(round22(val.x, val.y),
                                       round22(val.z, val.w));
    }
}

// ---------------------------------------------------------------------------
// 1-term HMMA GEMM mainloop (qkv): D = xh @ Wh. 256 thr, 8 warps 32x64.
// K-chunk 64, 3-stage pipeline (16 chunks).
// ---------------------------------------------------------------------------
__device__ __forceinline__ void stage_chunk64(
    const __half* __restrict__ Ah, const __half* __restrict__ BhT,
    int bm, int bn, int k0, int tid, uint32_t sbuf)
{
    for (int i = tid; i < 1024; i += 256) {
        int row = i >> 3, q = i & 7;
        uint32_t doff = (uint32_t)((row * G1STR + q * 8) * 2);
        cpa16(sbuf + doff,             Ah + (size_t)(bm + row) * HIDDEN + k0 + q * 8);
        cpa16(sbuf + G1BUF * 2 + doff, BhT + (size_t)(bn + row) * HIDDEN + k0 + q * 8);
    }
}

__device__ __forceinline__ void hmma_gemm_main1(
    const __half* __restrict__ Ah, const __half* __restrict__ BhT,
    int bm, int bn, int tid, uint32_t sbase, float acc[2][8][4])
{
    const int lane = tid & 31, wid = tid >> 5;
    const int m_off = (wid & 3) * 32, n_off = (wid >> 2) * 64;
    const int arow = lane & 15;
    const int acolb = (lane >> 4) << 3;
    const int brow = (lane & 7) + ((lane >> 4) << 3);
    const int bcolb = ((lane >> 3) & 1) << 3;
    const uint32_t bufbytes = 2 * G1BUF * 2;
    const int NCH = HIDDEN / 64;   // 16

    stage_chunk64(Ah, BhT, bm, bn, 0, tid, sbase);
    CP_COMMIT();
    stage_chunk64(Ah, BhT, bm, bn, 64, tid, sbase + bufbytes);
    CP_COMMIT();

    for (int c = 0; c < NCH; c++) {
        uint32_t cur = sbase + (uint32_t)(c % 3) * bufbytes;
        if (c + 1 < NCH) { CP_WAIT1(); } else { CP_WAIT0(); }
        __syncthreads();
        if (c + 2 < NCH) {
            stage_chunk64(Ah, BhT, bm, bn, (c + 2) * 64, tid,
                          sbase + (uint32_t)((c + 2) % 3) * bufbytes);
            CP_COMMIT();
        }

        uint32_t uAh = cur, uBh = cur + G1BUF * 2;
#pragma unroll
        for (int kk = 0; kk < 64; kk += 16) {
            uint32_t aH[2][4], bH[8][2];
#pragma unroll
            for (int t = 0; t < 2; t++) {
                uint32_t off = (uint32_t)(((m_off + t * 16 + arow) * G1STR
                                           + kk + acolb) * 2);
                ldm4(aH[t][0], aH[t][1], aH[t][2], aH[t][3], uAh + off);
            }
#pragma unroll
            for (int p = 0; p < 4; p++) {
                uint32_t off = (uint32_t)(((n_off + p * 16 + brow) * G1STR
                                           + kk + bcolb) * 2);
                ldm4(bH[2 * p][0], bH[2 * p][1], bH[2 * p + 1][0], bH[2 * p + 1][1],
                     uBh + off);
            }
#pragma unroll
            for (int mt = 0; mt < 2; mt++)
#pragma unroll
                for (int nt = 0; nt < 8; nt++)
                    mma_f16(acc[mt][nt], aH[mt], bH[nt]);
        }
    }
}

// ---------------------------------------------------------------------------
// 2-term HMMA GEMM mainloop (out-proj): D = (Ah+Al) @ Bh  (round-14, proven)
// ---------------------------------------------------------------------------
__device__ __forceinline__ void stage_chunk3(
    const __half* __restrict__ Ah, const __half* __restrict__ Al,
    const __half* __restrict__ BhT,
    int bm, int bn, int k0, int tid, uint32_t sbuf)
{
    for (int i = tid; i < 512; i += 256) {
        int row = i >> 2, q = i & 3;
        uint32_t doff = (uint32_t)((row * ASTR + q * 8) * 2);
        size_t soA = (size_t)(bm + row) * HIDDEN + k0 + q * 8;
        size_t soB = (size_t)(bn + row) * HIDDEN + k0 + q * 8;
        cpa16(sbuf + doff,                Ah + soA);
        cpa16(sbuf + BUFH * 2 + doff,     Al + soA);
        cpa16(sbuf + 2 * BUFH * 2 + doff, BhT + soB);
    }
}

__device__ __forceinline__ void hmma_gemm_main2(
    const __half* __restrict__ Ah, const __half* __restrict__ Al,
    const __half* __restrict__ BhT,
    int bm, int bn, int tid, uint32_t sbase,
    float acc[2][8][4], uint32_t accH[2][8][2])
{
    const int lane = tid & 31, wid = tid >> 5;
    const int m_off = (wid & 3) * 32, n_off = (wid >> 2) * 64;
    const int arow = lane & 15;
    const int acolb = (lane >> 4) << 3;
    const int brow = (lane & 7) + ((lane >> 4) << 3);
    const int bcolb = ((lane >> 3) & 1) << 3;
    const uint32_t bufbytes = 3 * BUFH * 2;

    stage_chunk3(Ah, Al, BhT, bm, bn, 0, tid, sbase);
    CP_COMMIT();
    stage_chunk3(Ah, Al, BhT, bm, bn, 32, tid, sbase + bufbytes);
    CP_COMMIT();

    for (int c = 0; c < 32; c++) {
        uint32_t cur = sbase + (uint32_t)(c % 3) * bufbytes;
        if (c + 1 < 32) { CP_WAIT1(); } else { CP_WAIT0(); }
        __syncthreads();
        if (c + 2 < 32) {
            stage_chunk3(Ah, Al, BhT, bm, bn, (c + 2) * 32, tid,
                         sbase + (uint32_t)((c + 2) % 3) * bufbytes);
            CP_COMMIT();
        }

        uint32_t uAh = cur, uAl = cur + BUFH * 2;
        uint32_t uBh = cur + 2 * BUFH * 2;
#pragma unroll
        for (int kk = 0; kk < 32; kk += 16) {
            uint32_t aH[2][4], aL[2][4], bH[8][2];
#pragma unroll
            for (int t = 0; t < 2; t++) {
                uint32_t off = (uint32_t)(((m_off + t * 16 + arow) * ASTR
                                           + kk + acolb) * 2);
                ldm4(aH[t][0], aH[t][1], aH[t][2], aH[t][3], uAh + off);
                ldm4(aL[t][0], aL[t][1], aL[t][2], aL[t][3], uAl + off);
            }
#pragma unroll
            for (int p = 0; p < 4; p++) {
                uint32_t off = (uint32_t)(((n_off + p * 16 + brow) * ASTR
                                           + kk + bcolb) * 2);
                ldm4(bH[2 * p][0], bH[2 * p][1], bH[2 * p + 1][0], bH[2 * p + 1][1],
                     uBh + off);
            }
#pragma unroll
            for (int mt = 0; mt < 2; mt++)
#pragma unroll
                for (int nt = 0; nt < 8; nt++) {
                    mma_f16(acc[mt][nt], aH[mt], bH[nt]);
                    mma_f16a(accH[mt][nt], aL[mt], bH[nt]);
                }
        }
    }
}

// ---------------------------------------------------------------------------
// GEMM 1 (1-term): qkv = xh @ Wh + b -> fp32 q/k/v outputs (plain epilogue)
// ---------------------------------------------------------------------------
__global__ __launch_bounds__(256, 1) void gemm_qkv_mma(
    const float* __restrict__ bias,
    float* __restrict__ qo, float* __restrict__ ko, float* __restrict__ vo)
{
    extern __shared__ __half dynsm[];
    int tid = threadIdx.x, lane = tid & 31, wid = tid >> 5;
    int bm = blockIdx.y * 128, bn = blockIdx.x * 128;
    float acc[2][8][4] = {};

    hmma_gemm_main1(g_xh, g_wqkvT_h, bm, bn, tid, smem_u32(dynsm), acc);

    const int m_off = (wid & 3) * 32, n_off = (wid >> 2) * 64;
    int r = lane >> 2, c2 = (lane & 3) << 1;
#pragma unroll
    for (int mt = 0; mt < 2; mt++) {
        int m0 = bm + m_off + mt * 16 + r;
        int m1 = m0 + 8;
        int bb0 = m0 >> 11, s0 = m0 & (SEQ - 1);
        int bb1 = m1 >> 11, s1 = m1 & (SEQ - 1);
#pragma unroll
        for (int nt = 0; nt < 8; nt++) {
            int n = bn + n_off + nt * 8 + c2;
            float2 bv = *(const float2*)&bias[n];
            int t = n >> 10, hh = (n >> 6) & 15, dc = n & 63;
            float* base = (t == 0) ? qo : ((t == 1) ? ko : vo);
            size_t off0 = ((size_t)(bb0 * NHEADS + hh) * SEQ + s0) * HDIM + dc;
            size_t off1 = ((size_t)(bb1 * NHEADS + hh) * SEQ + s1) * HDIM + dc;
            *(float2*)&base[off0] =
                make_float2(acc[mt][nt][0] + bv.x, acc[mt][nt][1] + bv.y);
            *(float2*)&base[off1] =
                make_float2(acc[mt][nt][2] + bv.x, acc[mt][nt][3] + bv.y);
        }
    }
}

// ---------------------------------------------------------------------------
// GEMM 2: output = (ctxh+ctxl) @ Wouth + b_out (2-term)
// ---------------------------------------------------------------------------
__global__ __launch_bounds__(256, 1) void gemm_out_mma(
    const float* __restrict__ bias, float* __restrict__ C)
{
    extern __shared__ __half dynsm[];
    int tid = threadIdx.x, lane = tid & 31, wid = tid >> 5;
    int bm = blockIdx.y * 128, bn = blockIdx.x * 128;
    float acc[2][8][4] = {};
    uint32_t accH[2][8][2] = {};

    hmma_gemm_main2(g_ctxh, g_ctxl, g_woutT_h, bm, bn, tid,
                    smem_u32(dynsm), acc, accH);

    const int m_off = (wid & 3) * 32, n_off = (wid >> 2) * 64;
    int r = lane >> 2, c2 = (lane & 3) << 1;
#pragma unroll
    for (int mt = 0; mt < 2; mt++) {
        int m0 = bm + m_off + mt * 16 + r;
        int m1 = m0 + 8;
#pragma unroll
        for (int nt = 0; nt < 8; nt++) {
            merge_res(acc[mt][nt], accH[mt][nt]);
            int n = bn + n_off + nt * 8 + c2;
            float2 bv = *(const float2*)&bias[n];
            *(float2*)&C[(size_t)m0 * HIDDEN + n] =
                make_float2(acc[mt][nt][0] + bv.x, acc[mt][nt][1] + bv.y);
            *(float2*)&C[(size_t)m1 * HIDDEN + n] =
                make_float2(acc[mt][nt][2] + bv.x, acc[mt][nt][3] + bv.y);
        }
    }
}

// ---------------------------------------------------------------------------
// Flash attention on HMMA (round-14, proven): 2-term S, 2-term PV.
// ---------------------------------------------------------------------------
#define KT 64
#define QT 128
#define AST2 72
#define QARR (128 * AST2)
#define KV_OFF QARR
#define ARR2 (64 * AST2)
#define KVBUF (3 * ARR2)
#define NKV 3
#define ATTN_SMEM_BYTES ((KV_OFF + NKV * KVBUF) * 2 + 2 * 64 * 4)

__device__ __forceinline__ void stage_kv(
    const __half* Kh, const __half* Kl, const __half* Vh,
    int k0, int tid, uint32_t sbuf)
{
    for (int i = tid; i < 512; i += 256) {
        int row = i >> 3, q = i & 7;
        uint32_t doff = (uint32_t)((row * AST2 + q * 8) * 2);
        size_t src = (size_t)(k0 + row) * HDIM + q * 8;
        cpa16(sbuf + doff,                Kh + src);
        cpa16(sbuf + ARR2 * 2 + doff,     Kl + src);
        cpa16(sbuf + 2 * ARR2 * 2 + doff, Vh + src);
    }
}

__global__ __launch_bounds__(256, 1) void attn_mma(const int* __restrict__ mask)
{
    extern __shared__ __half asm_[];
    uint32_t sb = smem_u32(asm_);
    float* mbias = (float*)(asm_ + KV_OFF + NKV * KVBUF);
    int tid = threadIdx.x, lane = tid & 31, wid = tid >> 5;
    int qt = gridDim.x - 1 - blockIdx.x;      // long tiles first
    int h = blockIdx.y, b = blockIdx.z;
    int bh = b * NHEADS + h;
    int qbase = qt * QT;
    size_t qoff = ((size_t)bh * SEQ + qbase) * HDIM;
    const __half* Qh = g_qh + qoff;
    size_t kvoff = (size_t)bh * SEQ * HDIM;
    const __half *Kh = g_kh + kvoff, *Kl = g_kl + kvoff;
    const __half *Vh = g_vh + kvoff;

    for (int i = tid; i < 1024; i += 256) {
        int row = i >> 3, q = i & 7;
        uint32_t doff = (uint32_t)((row * AST2 + q * 8) * 2);
        cpa16(sb + doff, Qh + (size_t)row * HDIM + q * 8);
    }
    CP_COMMIT();

    const int nkt = 2 * qt + 2;
    stage_kv(Kh, Kl, Vh, 0, tid, sb + KV_OFF * 2);
    CP_COMMIT();
    stage_kv(Kh, Kl, Vh, KT, tid, sb + (KV_OFF + KVBUF) * 2);
    CP_COMMIT();
    CP_WAIT2();          // Q ready
    __syncthreads();

    const int m_off = wid * 16;
    uint32_t qah[4][4];
    {
        int row = m_off + (lane & 15);
        int colb = 8 * (lane >> 4);
#pragma unroll
        for (int kt2 = 0; kt2 < 4; kt2++) {
            uint32_t a = sb + (uint32_t)((row * AST2 + kt2 * 16 + colb) * 2);
            ldm4(qah[kt2][0], qah[kt2][1], qah[kt2][2], qah[kt2][3], a);
        }
    }

    float o[8][4] = {};
    float m0 = -1e30f, m1 = -1e30f, l0 = 0.f, l1 = 0.f;
    const int g = lane >> 2, c2 = (lane & 3) << 1;
    const int brow = (lane & 7) + ((lane >> 4) << 3);
    const int bcolb = ((lane >> 3) & 1) << 3;
    const int vrow = lane & 15, vcolb = 8 * (lane >> 4);
    const int row0 = qbase + m_off + g, row1 = row0 + 8;

    for (int c = 0; c < nkt; c++) {
        uint32_t cur = sb + (uint32_t)((KV_OFF + (c % 3) * KVBUF) * 2);
        if (c + 1 < nkt) { CP_WAIT1(); } else { CP_WAIT0(); }
        if (tid < 64)
            mbias[(c & 1) * 64 + tid] =
                (mask[b * SEQ + c * KT + tid] == 0) ? -1e30f : 0.0f;
        __syncthreads();
        if (c + 2 < nkt) {
            stage_kv(Kh, Kl, Vh, (c + 2) * KT, tid,
                     sb + (uint32_t)((KV_OFF + ((c + 2) % 3) * KVBUF) * 2));
            CP_COMMIT();
        }

        uint32_t uKh = cur, uKl = cur + ARR2 * 2;
        uint32_t uVh = cur + 2 * ARR2 * 2;

        // ---- S = qh (kh + kl)^T : 2-term ----
        float s[8][4] = {};
        uint32_t sres[8][2] = {};
#pragma unroll
        for (int kk2 = 0; kk2 < 4; kk2++) {
            uint32_t kbh[4][4], kbl[4][4];
#pragma unroll
            for (int p = 0; p < 4; p++) {
                uint32_t a = (uint32_t)(((p * 16 + brow) * AST2
                                         + kk2 * 16 + bcolb) * 2);
                ldm4(kbh[p][0], kbh[p][1], kbh[p][2], kbh[p][3], uKh + a);
                ldm4(kbl[p][0], kbl[p][1], kbl[p][2], kbl[p][3], uKl + a);
            }
#pragma unroll
            for (int nt = 0; nt < 8; nt++) {
                int p = nt >> 1, ix = (nt & 1) * 2;
                mma_f16(s[nt], qah[kk2], &kbh[p][ix]);
                mma_f16a(sres[nt], qah[kk2], &kbl[p][ix]);
            }
        }
#pragma unroll
        for (int nt = 0; nt < 8; nt++) merge_res(s[nt], sres[nt]);

        // ---- mask + causal ----
        int k0 = c * KT;
        bool diag = (k0 + KT - 1 > row0) || (k0 + KT - 1 > row1);
#pragma unroll
        for (int nt = 0; nt < 8; nt++) {
            int colb = k0 + nt * 8 + c2;
            float mb0 = mbias[(c & 1) * 64 + nt * 8 + c2];
            float mb1 = mbias[(c & 1) * 64 + nt * 8 + c2 + 1];
            s[nt][0] += mb0; s[nt][1] += mb1;
            s[nt][2] += mb0; s[nt][3] += mb1;
            if (diag) {
                if (colb     > row0) s[nt][0] = -1e30f;
                if (colb + 1 > row0) s[nt][1] = -1e30f;
                if (colb     > row1) s[nt][2] = -1e30f;
                if (colb + 1 > row1) s[nt][3] = -1e30f;
            }
        }

        // ---- online softmax ----
        float mx0 = -1e30f, mx1 = -1e30f;
#pragma unroll
        for (int nt = 0; nt < 8; nt++) {
            mx0 = fmaxf(mx0, fmaxf(s[nt][0], s[nt][1]));
            mx1 = fmaxf(mx1, fmaxf(s[nt][2], s[nt][3]));
        }
        mx0 = fmaxf(mx0, __shfl_xor_sync(0xffffffffu, mx0, 1));
        mx0 = fmaxf(mx0, __shfl_xor_sync(0xffffffffu, mx0, 2));
        mx1 = fmaxf(mx1, __shfl_xor_sync(0xffffffffu, mx1, 1));
        mx1 = fmaxf(mx1, __shfl_xor_sync(0xffffffffu, mx1, 2));
        float mn0 = fmaxf(m0, mx0), mn1 = fmaxf(m1, mx1);
        float fac0 = __expf(m0 - mn0), fac1 = __expf(m1 - mn1);
        m0 = mn0; m1 = mn1;
        float rs0 = 0.f, rs1 = 0.f;
#pragma unroll
        for (int nt = 0; nt < 8; nt++) {
            s[nt][0] = __expf(s[nt][0] - mn0); rs0 += s[nt][0];
            s[nt][1] = __expf(s[nt][1] - mn0); rs0 += s[nt][1];
            s[nt][2] = __expf(s[nt][2] - mn1); rs1 += s[nt][2];
            s[nt][3] = __expf(s[nt][3] - mn1); rs1 += s[nt][3];
        }
        rs0 += __shfl_xor_sync(0xffffffffu, rs0, 1);
        rs0 += __shfl_xor_sync(0xffffffffu, rs0, 2);
        rs1 += __shfl_xor_sync(0xffffffffu, rs1, 1);
        rs1 += __shfl_xor_sync(0xffffffffu, rs1, 2);
        l0 = l0 * fac0 + rs0;
        l1 = l1 * fac1 + rs1;
#pragma unroll
        for (int nt = 0; nt < 8; nt++) {
            o[nt][0] *= fac0; o[nt][1] *= fac0;
            o[nt][2] *= fac1; o[nt][3] *= fac1;
        }

        // ---- P fragments (split P: h + l) ----
        uint32_t pah[4][4], pal[4][4];
#pragma unroll
        for (int kt2 = 0; kt2 < 4; kt2++) {
            split22(s[2 * kt2][0],     s[2 * kt2][1],     pah[kt2][0], pal[kt2][0]);
            split22(s[2 * kt2][2],     s[2 * kt2][3],     pah[kt2][1], pal[kt2][1]);
            split22(s[2 * kt2 + 1][0], s[2 * kt2 + 1][1], pah[kt2][2], pal[kt2][2]);
            split22(s[2 * kt2 + 1][2], s[2 * kt2 + 1][3], pah[kt2][3], pal[kt2][3]);
        }

        // ---- O += (Ph + Pl) Vh : 2-term ----
        uint32_t ores[8][2] = {};
#pragma unroll
        for (int kk2 = 0; kk2 < 4; kk2++) {
            uint32_t vbh[4][4];
#pragma unroll
            for (int n0i = 0; n0i < 4; n0i++) {
                uint32_t a = (uint32_t)(((kk2 * 16 + vrow) * AST2
                                         + n0i * 16 + vcolb) * 2);
                ldm4t(vbh[n0i][0], vbh[n0i][1], vbh[n0i][2], vbh[n0i][3], uVh + a);
            }
#pragma unroll
            for (int nt = 0; nt < 8; nt++) {
                int n0i = nt >> 1, ix = (nt & 1) * 2;
                mma_f16(o[nt], pah[kk2], &vbh[n0i][ix]);
                mma_f16a(ores[nt], pal[kk2], &vbh[n0i][ix]);
            }
        }
#pragma unroll
        for (int nt = 0; nt < 8; nt++) merge_res(o[nt], ores[nt]);
    }

    // ---- epilogue: normalize, write ctx h/l ----
    float inv0 = 1.0f / l0, inv1 = 1.0f / l1;
    size_t base0 = ((size_t)(b * SEQ) + row0) * HIDDEN + h * HDIM + c2;
    size_t base1 = base0 + (size_t)8 * HIDDEN;
#pragma unroll
    for (int nt = 0; nt < 8; nt++) {
        uint32_t h2, l2;
        split22(o[nt][0] * inv0, o[nt][1] * inv0, h2, l2);
        *(uint32_t*)&g_ctxh[base0 + nt * 8] = h2;
        *(uint32_t*)&g_ctxl[base0 + nt * 8] = l2;
        split22(o[nt][2] * inv1, o[nt][3] * inv1, h2, l2);
        *(uint32_t*)&g_ctxh[base1 + nt * 8] = h2;
        *(uint32_t*)&g_ctxl[base1 + nt * 8] = l2;
    }
}

// ---------------------------------------------------------------------------
extern "C" void kernel_launch(void* const* d_in, const int* in_sizes, int n_in,
                              void* d_out, int out_size) {
    const float* x    = (const float*)d_in[0];
    const int*   mask = (const int*)d_in[1];
    const float* Wqkv = (const float*)d_in[2];
    const float* bqkv = (const float*)d_in[3];
    const float* Wout = (const float*)d_in[4];
    const float* bout = (const float*)d_in[5];

    float* out = (float*)d_out;                     // [B,S,H]
    float* qo = out + (size_t)MTOT * HIDDEN;        // [B,h,S,d]
    float* ko = qo + (size_t)MTOT * HIDDEN;
    float* vo = ko + (size_t)MTOT * HIDDEN;

    cudaFuncSetAttribute(gemm_qkv_mma,
                         cudaFuncAttributeMaxDynamicSharedMemorySize, GEMM1_SMEM_BYTES);
    cudaFuncSetAttribute(gemm_out_mma,
                         cudaFuncAttributeMaxDynamicSharedMemorySize, GEMM2_SMEM_BYTES);
    cudaFuncSetAttribute(attn_mma,
                         cudaFuncAttributeMaxDynamicSharedMemorySize, ATTN_SMEM_BYTES);

    __half *xh, *wqh, *woh;
    cudaGetSymbolAddress((void**)&xh, g_xh);
    cudaGetSymbolAddress((void**)&wqh, g_wqkvT_h);
    cudaGetSymbolAddress((void**)&woh, g_woutT_h);

    conv_x_round<<<(MTOT * HIDDEN / 4 + 255) / 256, 256>>>(
        x, xh, MTOT * HIDDEN / 4);
    conv_wT_kernel<<<dim3(3 * HIDDEN / 32, HIDDEN / 32), 256>>>(
        Wqkv, wqh, 3 * HIDDEN);
    conv_wT_kernel<<<dim3(HIDDEN / 32, HIDDEN / 32), 256>>>(
        Wout, woh, HIDDEN);

    gemm_qkv_mma<<<dim3(24, 32), 256, GEMM1_SMEM_BYTES>>>(bqkv, qo, ko, vo);
    conv_attn_split<<<3 * MTOT * HIDDEN / 4 / 256, 256>>>(qo, ko, vo);
    attn_mma<<<dim3(SEQ / QT, NHEADS, BATCH), 256, ATTN_SMEM_BYTES>>>(mask);
    gemm_out_mma<<<dim3(8, 32), 256, GEMM2_SMEM_BYTES>>>(bout, out);
}

// round 17
// speedup vs baseline: 1.6839x; 1.0367x over previous
#include <cuda_runtime.h>
#include <cuda_fp16.h>
#include <cstdint>

#define HIDDEN 1024
#define NHEADS 16
#define HDIM 64
#define BATCH 2
#define SEQ 2048
#define MTOT (BATCH*SEQ)

typedef unsigned long long ull;

// ---- fp16 scratch -----------------------------------------------------------
__device__ __half g_xh[(size_t)MTOT * HIDDEN];            // x rounded
__device__ __half g_wqkvT_h[(size_t)3 * HIDDEN * HIDDEN]; // Wqkv^T rounded
__device__ __half g_woutT_h[(size_t)HIDDEN * HIDDEN];     // Wout^T rounded
__device__ __half g_ctxh[(size_t)MTOT * HIDDEN];
__device__ __half g_ctxl[(size_t)MTOT * HIDDEN];
// attention operands, [B,h,S,d]; q pre-scaled by 0.125
__device__ __half g_qh[(size_t)MTOT * HIDDEN];   // q rounded (2-term S)
__device__ __half g_kh[(size_t)MTOT * HIDDEN];
__device__ __half g_kl[(size_t)MTOT * HIDDEN];
__device__ __half g_vh[(size_t)MTOT * HIDDEN];   // v rounded (2-term PV)

// ======================= helpers ============================================
__device__ __forceinline__ uint32_t smem_u32(const void* p) {
    uint32_t a;
    asm("{ .reg .u64 t; cvta.to.shared.u64 t, %1; cvt.u32.u64 %0, t; }"
        : "=r"(a) : "l"(p));
    return a;
}
__device__ __forceinline__ void ldm4(uint32_t& r0, uint32_t& r1,
                                     uint32_t& r2, uint32_t& r3, uint32_t a) {
    asm volatile("ldmatrix.sync.aligned.m8n8.x4.shared.b16 {%0,%1,%2,%3}, [%4];"
                 : "=r"(r0), "=r"(r1), "=r"(r2), "=r"(r3) : "r"(a));
}
__device__ __forceinline__ void ldm4t(uint32_t& r0, uint32_t& r1,
                                      uint32_t& r2, uint32_t& r3, uint32_t a) {
    asm volatile("ldmatrix.sync.aligned.m8n8.x4.trans.shared.b16 {%0,%1,%2,%3}, [%4];"
                 : "=r"(r0), "=r"(r1), "=r"(r2), "=r"(r3) : "r"(a));
}
__device__ __forceinline__ void mma_f16(float d[4], const uint32_t a[4],
                                        const uint32_t b[2]) {
    asm volatile(
        "mma.sync.aligned.m16n8k16.row.col.f32.f16.f16.f32 "
        "{%0,%1,%2,%3}, {%4,%5,%6,%7}, {%8,%9}, {%0,%1,%2,%3};"
        : "+f"(d[0]), "+f"(d[1]), "+f"(d[2]), "+f"(d[3])
        : "r"(a[0]), "r"(a[1]), "r"(a[2]), "r"(a[3]), "r"(b[0]), "r"(b[1]));
}
__device__ __forceinline__ void mma_f16a(uint32_t d[2], const uint32_t a[4],
                                         const uint32_t b[2]) {
    asm volatile(
        "mma.sync.aligned.m16n8k16.row.col.f16.f16.f16.f16 "
        "{%0,%1}, {%2,%3,%4,%5}, {%6,%7}, {%0,%1};"
        : "+r"(d[0]), "+r"(d[1])
        : "r"(a[0]), "r"(a[1]), "r"(a[2]), "r"(a[3]), "r"(b[0]), "r"(b[1]));
}
__device__ __forceinline__ void merge_res(float acc[4], const uint32_t r[2]) {
    __half2 h0 = *(const __half2*)&r[0];
    __half2 h1 = *(const __half2*)&r[1];
    float2 f0 = __half22float2(h0), f1 = __half22float2(h1);
    acc[0] += f0.x; acc[1] += f0.y;
    acc[2] += f1.x; acc[3] += f1.y;
}
__device__ __forceinline__ void cpa16(uint32_t dst, const void* src) {
    asm volatile("cp.async.cg.shared.global [%0], [%1], 16;"
                 :: "r"(dst), "l"(src) : "memory");
}
#define CP_COMMIT() asm volatile("cp.async.commit_group;" ::: "memory")
#define CP_WAIT2()  asm volatile("cp.async.wait_group 2;" ::: "memory")
#define CP_WAIT1()  asm volatile("cp.async.wait_group 1;" ::: "memory")
#define CP_WAIT0()  asm volatile("cp.async.wait_group 0;" ::: "memory")

__device__ __forceinline__ void split22(float a, float b, uint32_t& h, uint32_t& l) {
    __half2 hh = __floats2half2_rn(a, b);
    float2 f = __half22float2(hh);
    __half2 ll = __floats2half2_rn(a - f.x, b - f.y);
    h = *(uint32_t*)&hh;
    l = *(uint32_t*)&ll;
}
__device__ __forceinline__ uint32_t round22(float a, float b) {
    __half2 hh = __floats2half2_rn(a, b);
    return *(uint32_t*)&hh;
}

// qkv gemm: 1-term, K-chunk 128, stride 136 halves
#define G1STR 136
#define G1BUF (128 * G1STR)
#define G1CH 128
#define G1NCH (HIDDEN / G1CH)              // 8
#define GEMM1_SMEM_BYTES (3 * 2 * G1BUF * 2)   // 208896
// out gemm: 2-term, K-chunk 64, stride 72 halves
#define G2STR 72
#define G2BUF (128 * G2STR)
#define G2CH 64
#define G2NCH (HIDDEN / G2CH)              // 16
#define GEMM2_SMEM_BYTES (3 * 3 * G2BUF * 2)   // 165888

// ---------------------------------------------------------------------------
// Conversion kernels
// ---------------------------------------------------------------------------
__global__ __launch_bounds__(256) void conv_x_round(
    const float* __restrict__ src, __half* __restrict__ dh, int n4)
{
    int i = blockIdx.x * 256 + threadIdx.x;
    if (i >= n4) return;
    float4 v = ((const float4*)src)[i];
    ((uint2*)dh)[i] = make_uint2(round22(v.x, v.y), round22(v.z, v.w));
}

__global__ __launch_bounds__(256) void conv_wT_kernel(
    const float* __restrict__ W, __half* __restrict__ WhT, int N)
{
    __shared__ float ts[32][33];
    int n0 = blockIdx.x * 32, k0 = blockIdx.y * 32;
    int tx = threadIdx.x & 31, ty = threadIdx.x >> 5;
#pragma unroll
    for (int r = 0; r < 32; r += 8)
        ts[ty + r][tx] = W[(size_t)(k0 + ty + r) * N + n0 + tx];
    __syncthreads();
#pragma unroll
    for (int r = 0; r < 32; r += 8) {
        float v = ts[tx][ty + r];
        size_t o = (size_t)(n0 + ty + r) * HIDDEN + k0 + tx;
        WhT[o] = __float2half_rn(v);
    }
}

// q/k/v fp32 [B,h,S,d] -> fp16 (q: h only, scaled 1/8; k: h+l; v: h only)
__global__ __launch_bounds__(256) void conv_attn_split(
    const float* __restrict__ q, const float* __restrict__ k,
    const float* __restrict__ v)
{
    const int n4 = MTOT * HIDDEN / 4;
    int i = blockIdx.x * 256 + threadIdx.x;
    int region = i / n4;
    int j = i - region * n4;
    if (region == 0) {
        float4 val = ((const float4*)q)[j];
        ((uint2*)g_qh)[j] = make_uint2(round22(val.x * 0.125f, val.y * 0.125f),
                                       round22(val.z * 0.125f, val.w * 0.125f));
    } else if (region == 1) {
        float4 val = ((const float4*)k)[j];
        uint32_t h0, l0, h1, l1;
        split22(val.x, val.y, h0, l0);
        split22(val.z, val.w, h1, l1);
        ((uint2*)g_kh)[j] = make_uint2(h0, h1);
        ((uint2*)g_kl)[j] = make_uint2(l0, l1);
    } else {
        float4 val = ((const float4*)v)[j];
        ((uint2*)g_vh)[j] = make_uint2(round22(val.x, val.y),
                                       round22(val.z, val.w));
    }
}

// ---------------------------------------------------------------------------
// 1-term HMMA GEMM mainloop (qkv): D = xh @ Wh. 256 thr, 8 warps 32x64.
// K-chunk 128, 3-stage pipeline (8 chunks).
// ---------------------------------------------------------------------------
__device__ __forceinline__ void stage_chunk128(
    const __half* __restrict__ Ah, const __half* __restrict__ BhT,
    int bm, int bn, int k0, int tid, uint32_t sbuf)
{
    for (int i = tid; i < 2048; i += 256) {
        int row = i >> 4, q = i & 15;
        uint32_t doff = (uint32_t)((row * G1STR + q * 8) * 2);
        cpa16(sbuf + doff,             Ah + (size_t)(bm + row) * HIDDEN + k0 + q * 8);
        cpa16(sbuf + G1BUF * 2 + doff, BhT + (size_t)(bn + row) * HIDDEN + k0 + q * 8);
    }
}

__device__ __forceinline__ void hmma_gemm_main1(
    const __half* __restrict__ Ah, const __half* __restrict__ BhT,
    int bm, int bn, int tid, uint32_t sbase, float acc[2][8][4])
{
    const int lane = tid & 31, wid = tid >> 5;
    const int m_off = (wid & 3) * 32, n_off = (wid >> 2) * 64;
    const int arow = lane & 15;
    const int acolb = (lane >> 4) << 3;
    const int brow = (lane & 7) + ((lane >> 4) << 3);
    const int bcolb = ((lane >> 3) & 1) << 3;
    const uint32_t bufbytes = 2 * G1BUF * 2;

    stage_chunk128(Ah, BhT, bm, bn, 0, tid, sbase);
    CP_COMMIT();
    stage_chunk128(Ah, BhT, bm, bn, G1CH, tid, sbase + bufbytes);
    CP_COMMIT();

    for (int c = 0; c < G1NCH; c++) {
        uint32_t cur = sbase + (uint32_t)(c % 3) * bufbytes;
        if (c + 1 < G1NCH) { CP_WAIT1(); } else { CP_WAIT0(); }
        __syncthreads();
        if (c + 2 < G1NCH) {
            stage_chunk128(Ah, BhT, bm, bn, (c + 2) * G1CH, tid,
                           sbase + (uint32_t)((c + 2) % 3) * bufbytes);
            CP_COMMIT();
        }

        uint32_t uAh = cur, uBh = cur + G1BUF * 2;
#pragma unroll
        for (int kk = 0; kk < G1CH; kk += 16) {
            uint32_t aH[2][4], bH[8][2];
#pragma unroll
            for (int t = 0; t < 2; t++) {
                uint32_t off = (uint32_t)(((m_off + t * 16 + arow) * G1STR
                                           + kk + acolb) * 2);
                ldm4(aH[t][0], aH[t][1], aH[t][2], aH[t][3], uAh + off);
            }
#pragma unroll
            for (int p = 0; p < 4; p++) {
                uint32_t off = (uint32_t)(((n_off + p * 16 + brow) * G1STR
                                           + kk + bcolb) * 2);
                ldm4(bH[2 * p][0], bH[2 * p][1], bH[2 * p + 1][0], bH[2 * p + 1][1],
                     uBh + off);
            }
#pragma unroll
            for (int mt = 0; mt < 2; mt++)
#pragma unroll
                for (int nt = 0; nt < 8; nt++)
                    mma_f16(acc[mt][nt], aH[mt], bH[nt]);
        }
    }
}

// ---------------------------------------------------------------------------
// 2-term HMMA GEMM mainloop (out-proj): D = (Ah+Al) @ Bh. K-chunk 64.
// ---------------------------------------------------------------------------
__device__ __forceinline__ void stage_chunk64x3(
    const __half* __restrict__ Ah, const __half* __restrict__ Al,
    const __half* __restrict__ BhT,
    int bm, int bn, int k0, int tid, uint32_t sbuf)
{
    for (int i = tid; i < 1024; i += 256) {
        int row = i >> 3, q = i & 7;
        uint32_t doff = (uint32_t)((row * G2STR + q * 8) * 2);
        size_t soA = (size_t)(bm + row) * HIDDEN + k0 + q * 8;
        size_t soB = (size_t)(bn + row) * HIDDEN + k0 + q * 8;
        cpa16(sbuf + doff,                 Ah + soA);
        cpa16(sbuf + G2BUF * 2 + doff,     Al + soA);
        cpa16(sbuf + 2 * G2BUF * 2 + doff, BhT + soB);
    }
}

__device__ __forceinline__ void hmma_gemm_main2(
    const __half* __restrict__ Ah, const __half* __restrict__ Al,
    const __half* __restrict__ BhT,
    int bm, int bn, int tid, uint32_t sbase,
    float acc[2][8][4], uint32_t accH[2][8][2])
{
    const int lane = tid & 31, wid = tid >> 5;
    const int m_off = (wid & 3) * 32, n_off = (wid >> 2) * 64;
    const int arow = lane & 15;
    const int acolb = (lane >> 4) << 3;
    const int brow = (lane & 7) + ((lane >> 4) << 3);
    const int bcolb = ((lane >> 3) & 1) << 3;
    const uint32_t bufbytes = 3 * G2BUF * 2;

    stage_chunk64x3(Ah, Al, BhT, bm, bn, 0, tid, sbase);
    CP_COMMIT();
    stage_chunk64x3(Ah, Al, BhT, bm, bn, G2CH, tid, sbase + bufbytes);
    CP_COMMIT();

    for (int c = 0; c < G2NCH; c++) {
        uint32_t cur = sbase + (uint32_t)(c % 3) * bufbytes;
        if (c + 1 < G2NCH) { CP_WAIT1(); } else { CP_WAIT0(); }
        __syncthreads();
        if (c + 2 < G2NCH) {
            stage_chunk64x3(Ah, Al, BhT, bm, bn, (c + 2) * G2CH, tid,
                            sbase + (uint32_t)((c + 2) % 3) * bufbytes);
            CP_COMMIT();
        }

        uint32_t uAh = cur, uAl = cur + G2BUF * 2;
        uint32_t uBh = cur + 2 * G2BUF * 2;
#pragma unroll
        for (int kk = 0; kk < G2CH; kk += 16) {
            uint32_t aH[2][4], aL[2][4], bH[8][2];
#pragma unroll
            for (int t = 0; t < 2; t++) {
                uint32_t off = (uint32_t)(((m_off + t * 16 + arow) * G2STR
                                           + kk + acolb) * 2);
                ldm4(aH[t][0], aH[t][1], aH[t][2], aH[t][3], uAh + off);
                ldm4(aL[t][0], aL[t][1], aL[t][2], aL[t][3], uAl + off);
            }
#pragma unroll
            for (int p = 0; p < 4; p++) {
                uint32_t off = (uint32_t)(((n_off + p * 16 + brow) * G2STR
                                           + kk + bcolb) * 2);
                ldm4(bH[2 * p][0], bH[2 * p][1], bH[2 * p + 1][0], bH[2 * p + 1][1],
                     uBh + off);
            }
#pragma unroll
            for (int mt = 0; mt < 2; mt++)
#pragma unroll
                for (int nt = 0; nt < 8; nt++) {
                    mma_f16(acc[mt][nt], aH[mt], bH[nt]);
                    mma_f16a(accH[mt][nt], aL[mt], bH[nt]);
                }
        }
    }
}

// ---------------------------------------------------------------------------
// GEMM 1 (1-term): qkv = xh @ Wh + b -> fp32 q/k/v outputs
// ---------------------------------------------------------------------------
__global__ __launch_bounds__(256, 1) void gemm_qkv_mma(
    const float* __restrict__ bias,
    float* __restrict__ qo, float* __restrict__ ko, float* __restrict__ vo)
{
    extern __shared__ __half dynsm[];
    int tid = threadIdx.x, lane = tid & 31, wid = tid >> 5;
    int bm = blockIdx.y * 128, bn = blockIdx.x * 128;
    float acc[2][8][4] = {};

    hmma_gemm_main1(g_xh, g_wqkvT_h, bm, bn, tid, smem_u32(dynsm), acc);

    const int m_off = (wid & 3) * 32, n_off = (wid >> 2) * 64;
    int r = lane >> 2, c2 = (lane & 3) << 1;
#pragma unroll
    for (int mt = 0; mt < 2; mt++) {
        int m0 = bm + m_off + mt * 16 + r;
        int m1 = m0 + 8;
        int bb0 = m0 >> 11, s0 = m0 & (SEQ - 1);
        int bb1 = m1 >> 11, s1 = m1 & (SEQ - 1);
#pragma unroll
        for (int nt = 0; nt < 8; nt++) {
            int n = bn + n_off + nt * 8 + c2;
            float2 bv = *(const float2*)&bias[n];
            int t = n >> 10, hh = (n >> 6) & 15, dc = n & 63;
            float* base = (t == 0) ? qo : ((t == 1) ? ko : vo);
            size_t off0 = ((size_t)(bb0 * NHEADS + hh) * SEQ + s0) * HDIM + dc;
            size_t off1 = ((size_t)(bb1 * NHEADS + hh) * SEQ + s1) * HDIM + dc;
            *(float2*)&base[off0] =
                make_float2(acc[mt][nt][0] + bv.x, acc[mt][nt][1] + bv.y);
            *(float2*)&base[off1] =
                make_float2(acc[mt][nt][2] + bv.x, acc[mt][nt][3] + bv.y);
        }
    }
}

// ---------------------------------------------------------------------------
// GEMM 2: output = (ctxh+ctxl) @ Wouth + b_out (2-term)
// ---------------------------------------------------------------------------
__global__ __launch_bounds__(256, 1) void gemm_out_mma(
    const float* __restrict__ bias, float* __restrict__ C)
{
    extern __shared__ __half dynsm[];
    int tid = threadIdx.x, lane = tid & 31, wid = tid >> 5;
    int bm = blockIdx.y * 128, bn = blockIdx.x * 128;
    float acc[2][8][4] = {};
    uint32_t accH[2][8][2] = {};

    hmma_gemm_main2(g_ctxh, g_ctxl, g_woutT_h, bm, bn, tid,
                    smem_u32(dynsm), acc, accH);

    const int m_off = (wid & 3) * 32, n_off = (wid >> 2) * 64;
    int r = lane >> 2, c2 = (lane & 3) << 1;
#pragma unroll
    for (int mt = 0; mt < 2; mt++) {
        int m0 = bm + m_off + mt * 16 + r;
        int m1 = m0 + 8;
#pragma unroll
        for (int nt = 0; nt < 8; nt++) {
            merge_res(acc[mt][nt], accH[mt][nt]);
            int n = bn + n_off + nt * 8 + c2;
            float2 bv = *(const float2*)&bias[n];
            *(float2*)&C[(size_t)m0 * HIDDEN + n] =
                make_float2(acc[mt][nt][0] + bv.x, acc[mt][nt][1] + bv.y);
            *(float2*)&C[(size_t)m1 * HIDDEN + n] =
                make_float2(acc[mt][nt][2] + bv.x, acc[mt][nt][3] + bv.y);
        }
    }
}

// ---------------------------------------------------------------------------
// Flash attention on HMMA (round-14, proven): 2-term S, 2-term PV.
// ---------------------------------------------------------------------------
#define KT 64
#define QT 128
#define AST2 72
#define QARR (128 * AST2)
#define KV_OFF QARR
#define ARR2 (64 * AST2)
#define KVBUF (3 * ARR2)
#define NKV 3
#define ATTN_SMEM_BYTES ((KV_OFF + NKV * KVBUF) * 2 + 2 * 64 * 4)

__device__ __forceinline__ void stage_kv(
    const __half* Kh, const __half* Kl, const __half* Vh,
    int k0, int tid, uint32_t sbuf)
{
    for (int i = tid; i < 512; i += 256) {
        int row = i >> 3, q = i & 7;
        uint32_t doff = (uint32_t)((row * AST2 + q * 8) * 2);
        size_t src = (size_t)(k0 + row) * HDIM + q * 8;
        cpa16(sbuf + doff,                Kh + src);
        cpa16(sbuf + ARR2 * 2 + doff,     Kl + src);
        cpa16(sbuf + 2 * ARR2 * 2 + doff, Vh + src);
    }
}

__global__ __launch_bounds__(256, 1) void attn_mma(const int* __restrict__ mask)
{
    extern __shared__ __half asm_[];
    uint32_t sb = smem_u32(asm_);
    float* mbias = (float*)(asm_ + KV_OFF + NKV * KVBUF);
    int tid = threadIdx.x, lane = tid & 31, wid = tid >> 5;
    int qt = gridDim.x - 1 - blockIdx.x;      // long tiles first
    int h = blockIdx.y, b = blockIdx.z;
    int bh = b * NHEADS + h;
    int qbase = qt * QT;
    size_t qoff = ((size_t)bh * SEQ + qbase) * HDIM;
    const __half* Qh = g_qh + qoff;
    size_t kvoff = (size_t)bh * SEQ * HDIM;
    const __half *Kh = g_kh + kvoff, *Kl = g_kl + kvoff;
    const __half *Vh = g_vh + kvoff;

    for (int i = tid; i < 1024; i += 256) {
        int row = i >> 3, q = i & 7;
        uint32_t doff = (uint32_t)((row * AST2 + q * 8) * 2);
        cpa16(sb + doff, Qh + (size_t)row * HDIM + q * 8);
    }
    CP_COMMIT();

    const int nkt = 2 * qt + 2;
    stage_kv(Kh, Kl, Vh, 0, tid, sb + KV_OFF * 2);
    CP_COMMIT();
    stage_kv(Kh, Kl, Vh, KT, tid, sb + (KV_OFF + KVBUF) * 2);
    CP_COMMIT();
    CP_WAIT2();          // Q ready
    __syncthreads();

    const int m_off = wid * 16;
    uint32_t qah[4][4];
    {
        int row = m_off + (lane & 15);
        int colb = 8 * (lane >> 4);
#pragma unroll
        for (int kt2 = 0; kt2 < 4; kt2++) {
            uint32_t a = sb + (uint32_t)((row * AST2 + kt2 * 16 + colb) * 2);
            ldm4(qah[kt2][0], qah[kt2][1], qah[kt2][2], qah[kt2][3], a);
        }
    }

    float o[8][4] = {};
    float m0 = -1e30f, m1 = -1e30f, l0 = 0.f, l1 = 0.f;
    const int g = lane >> 2, c2 = (lane & 3) << 1;
    const int brow = (lane & 7) + ((lane >> 4) << 3);
    const int bcolb = ((lane >> 3) & 1) << 3;
    const int vrow = lane & 15, vcolb = 8 * (lane >> 4);
    const int row0 = qbase + m_off + g, row1 = row0 + 8;

    for (int c = 0; c < nkt; c++) {
        uint32_t cur = sb + (uint32_t)((KV_OFF + (c % 3) * KVBUF) * 2);
        if (c + 1 < nkt) { CP_WAIT1(); } else { CP_WAIT0(); }
        if (tid < 64)
            mbias[(c & 1) * 64 + tid] =
                (mask[b * SEQ + c * KT + tid] == 0) ? -1e30f : 0.0f;
        __syncthreads();
        if (c + 2 < nkt) {
            stage_kv(Kh, Kl, Vh, (c + 2) * KT, tid,
                     sb + (uint32_t)((KV_OFF + ((c + 2) % 3) * KVBUF) * 2));
            CP_COMMIT();
        }

        uint32_t uKh = cur, uKl = cur + ARR2 * 2;
        uint32_t uVh = cur + 2 * ARR2 * 2;

        // ---- S = qh (kh + kl)^T : 2-term ----
        float s[8][4] = {};
        uint32_t sres[8][2] = {};
#pragma unroll
        for (int kk2 = 0; kk2 < 4; kk2++) {
            uint32_t kbh[4][4], kbl[4][4];
#pragma unroll
            for (int p = 0; p < 4; p++) {
                uint32_t a = (uint32_t)(((p * 16 + brow) * AST2
                                         + kk2 * 16 + bcolb) * 2);
                ldm4(kbh[p][0], kbh[p][1], kbh[p][2], kbh[p][3], uKh + a);
                ldm4(kbl[p][0], kbl[p][1], kbl[p][2], kbl[p][3], uKl + a);
            }
#pragma unroll
            for (int nt = 0; nt < 8; nt++) {
                int p = nt >> 1, ix = (nt & 1) * 2;
                mma_f16(s[nt], qah[kk2], &kbh[p][ix]);
                mma_f16a(sres[nt], qah[kk2], &kbl[p][ix]);
            }
        }
#pragma unroll
        for (int nt = 0; nt < 8; nt++) merge_res(s[nt], sres[nt]);

        // ---- mask + causal ----
        int k0 = c * KT;
        bool diag = (k0 + KT - 1 > row0) || (k0 + KT - 1 > row1);
#pragma unroll
        for (int nt = 0; nt < 8; nt++) {
            int colb = k0 + nt * 8 + c2;
            float mb0 = mbias[(c & 1) * 64 + nt * 8 + c2];
            float mb1 = mbias[(c & 1) * 64 + nt * 8 + c2 + 1];
            s[nt][0] += mb0; s[nt][1] += mb1;
            s[nt][2] += mb0; s[nt][3] += mb1;
            if (diag) {
                if (colb     > row0) s[nt][0] = -1e30f;
                if (colb + 1 > row0) s[nt][1] = -1e30f;
                if (colb     > row1) s[nt][2] = -1e30f;
                if (colb + 1 > row1) s[nt][3] = -1e30f;
            }
        }

        // ---- online softmax ----
        float mx0 = -1e30f, mx1 = -1e30f;
#pragma unroll
        for (int nt = 0; nt < 8; nt++) {
            mx0 = fmaxf(mx0, fmaxf(s[nt][0], s[nt][1]));
            mx1 = fmaxf(mx1, fmaxf(s[nt][2], s[nt][3]));
        }
        mx0 = fmaxf(mx0, __shfl_xor_sync(0xffffffffu, mx0, 1));
        mx0 = fmaxf(mx0, __shfl_xor_sync(0xffffffffu, mx0, 2));
        mx1 = fmaxf(mx1, __shfl_xor_sync(0xffffffffu, mx1, 1));
        mx1 = fmaxf(mx1, __shfl_xor_sync(0xffffffffu, mx1, 2));
        float mn0 = fmaxf(m0, mx0), mn1 = fmaxf(m1, mx1);
        float fac0 = __expf(m0 - mn0), fac1 = __expf(m1 - mn1);
        m0 = mn0; m1 = mn1;
        float rs0 = 0.f, rs1 = 0.f;
#pragma unroll
        for (int nt = 0; nt < 8; nt++) {
            s[nt][0] = __expf(s[nt][0] - mn0); rs0 += s[nt][0];
            s[nt][1] = __expf(s[nt][1] - mn0); rs0 += s[nt][1];
            s[nt][2] = __expf(s[nt][2] - mn1); rs1 += s[nt][2];
            s[nt][3] = __expf(s[nt][3] - mn1); rs1 += s[nt][3];
        }
        rs0 += __shfl_xor_sync(0xffffffffu, rs0, 1);
        rs0 += __shfl_xor_sync(0xffffffffu, rs0, 2);
        rs1 += __shfl_xor_sync(0xffffffffu, rs1, 1);
        rs1 += __shfl_xor_sync(0xffffffffu, rs1, 2);
        l0 = l0 * fac0 + rs0;
        l1 = l1 * fac1 + rs1;
#pragma unroll
        for (int nt = 0; nt < 8; nt++) {
            o[nt][0] *= fac0; o[nt][1] *= fac0;
            o[nt][2] *= fac1; o[nt][3] *= fac1;
        }

        // ---- P fragments (split P: h + l) ----
        uint32_t pah[4][4], pal[4][4];
#pragma unroll
        for (int kt2 = 0; kt2 < 4; kt2++) {
            split22(s[2 * kt2][0],     s[2 * kt2][1],     pah[kt2][0], pal[kt2][0]);
            split22(s[2 * kt2][2],     s[2 * kt2][3],     pah[kt2][1], pal[kt2][1]);
            split22(s[2 * kt2 + 1][0], s[2 * kt2 + 1][1], pah[kt2][2], pal[kt2][2]);
            split22(s[2 * kt2 + 1][2], s[2 * kt2 + 1][3], pah[kt2][3], pal[kt2][3]);
        }

        // ---- O += (Ph + Pl) Vh : 2-term ----
        uint32_t ores[8][2] = {};
#pragma unroll
        for (int kk2 = 0; kk2 < 4; kk2++) {
            uint32_t vbh[4][4];
#pragma unroll
            for (int n0i = 0; n0i < 4; n0i++) {
                uint32_t a = (uint32_t)(((kk2 * 16 + vrow) * AST2
                                         + n0i * 16 + vcolb) * 2);
                ldm4t(vbh[n0i][0], vbh[n0i][1], vbh[n0i][2], vbh[n0i][3], uVh + a);
            }
#pragma unroll
            for (int nt = 0; nt < 8; nt++) {
                int n0i = nt >> 1, ix = (nt & 1) * 2;
                mma_f16(o[nt], pah[kk2], &vbh[n0i][ix]);
                mma_f16a(ores[nt], pal[kk2], &vbh[n0i][ix]);
            }
        }
#pragma unroll
        for (int nt = 0; nt < 8; nt++) merge_res(o[nt], ores[nt]);
    }

    // ---- epilogue: normalize, write ctx h/l ----
    float inv0 = 1.0f / l0, inv1 = 1.0f / l1;
    size_t base0 = ((size_t)(b * SEQ) + row0) * HIDDEN + h * HDIM + c2;
    size_t base1 = base0 + (size_t)8 * HIDDEN;
#pragma unroll
    for (int nt = 0; nt < 8; nt++) {
        uint32_t h2, l2;
        split22(o[nt][0] * inv0, o[nt][1] * inv0, h2, l2);
        *(uint32_t*)&g_ctxh[base0 + nt * 8] = h2;
        *(uint32_t*)&g_ctxl[base0 + nt * 8] = l2;
        split22(o[nt][2] * inv1, o[nt][3] * inv1, h2, l2);
        *(uint32_t*)&g_ctxh[base1 + nt * 8] = h2;
        *(uint32_t*)&g_ctxl[base1 + nt * 8] = l2;
    }
}

// ---------------------------------------------------------------------------
extern "C" void kernel_launch(void* const* d_in, const int* in_sizes, int n_in,
                              void* d_out, int out_size) {
    const float* x    = (const float*)d_in[0];
    const int*   mask = (const int*)d_in[1];
    const float* Wqkv = (const float*)d_in[2];
    const float* bqkv = (const float*)d_in[3];
    const float* Wout = (const float*)d_in[4];
    const float* bout = (const float*)d_in[5];

    float* out = (float*)d_out;                     // [B,S,H]
    float* qo = out + (size_t)MTOT * HIDDEN;        // [B,h,S,d]
    float* ko = qo + (size_t)MTOT * HIDDEN;
    float* vo = ko + (size_t)MTOT * HIDDEN;

    cudaFuncSetAttribute(gemm_qkv_mma,
                         cudaFuncAttributeMaxDynamicSharedMemorySize, GEMM1_SMEM_BYTES);
    cudaFuncSetAttribute(gemm_out_mma,
                         cudaFuncAttributeMaxDynamicSharedMemorySize, GEMM2_SMEM_BYTES);
    cudaFuncSetAttribute(attn_mma,
                         cudaFuncAttributeMaxDynamicSharedMemorySize, ATTN_SMEM_BYTES);

    __half *xh, *wqh, *woh;
    cudaGetSymbolAddress((void**)&xh, g_xh);
    cudaGetSymbolAddress((void**)&wqh, g_wqkvT_h);
    cudaGetSymbolAddress((void**)&woh, g_woutT_h);

    conv_x_round<<<(MTOT * HIDDEN / 4 + 255) / 256, 256>>>(
        x, xh, MTOT * HIDDEN / 4);
    conv_wT_kernel<<<dim3(3 * HIDDEN / 32, HIDDEN / 32), 256>>>(
        Wqkv, wqh, 3 * HIDDEN);
    conv_wT_kernel<<<dim3(HIDDEN / 32, HIDDEN / 32), 256>>>(
        Wout, woh, HIDDEN);

    gemm_qkv_mma<<<dim3(24, 32), 256, GEMM1_SMEM_BYTES>>>(bqkv, qo, ko, vo);
    conv_attn_split<<<3 * MTOT * HIDDEN / 4 / 256, 256>>>(qo, ko, vo);
    attn_mma<<<dim3(SEQ / QT, NHEADS, BATCH), 256, ATTN_SMEM_BYTES>>>(mask);
    gemm_out_mma<<<dim3(8, 32), 256, GEMM2_SMEM_BYTES>>>(bout, out);
}